// round 5
// baseline (speedup 1.0000x reference)
#include <cuda_runtime.h>

#define FULLMASK 0xffffffffu

// ---------- packed f32x2 helpers (Blackwell sm_103a) ----------
__device__ __forceinline__ unsigned long long pk2(float a, float b) {
    unsigned long long r;
    asm("mov.b64 %0, {%1, %2};" : "=l"(r) : "f"(a), "f"(b));
    return r;
}
__device__ __forceinline__ float2 upk2(unsigned long long v) {
    float2 r;
    asm("mov.b64 {%0, %1}, %2;" : "=f"(r.x), "=f"(r.y) : "l"(v));
    return r;
}
__device__ __forceinline__ unsigned long long ffma2(unsigned long long a,
                                                    unsigned long long b,
                                                    unsigned long long c) {
    unsigned long long d;
    asm("fma.rn.f32x2 %0, %1, %2, %3;" : "=l"(d) : "l"(a), "l"(b), "l"(c));
    return d;
}
__device__ __forceinline__ unsigned long long add2(unsigned long long a,
                                                   unsigned long long b) {
    unsigned long long d;
    asm("add.rn.f32x2 %0, %1, %2;" : "=l"(d) : "l"(a), "l"(b));
    return d;
}

// tanh(x) = 1 - 2/(exp(2x)+1) via MUFU.EX2 + MUFU.RCP (abs err ~1e-7)
__device__ __forceinline__ float tanh_fast(float xx) {
    float e;
    asm("ex2.approx.f32 %0, %1;" : "=f"(e) : "f"(xx * 2.8853900817779268f));
    float r;
    asm("rcp.approx.f32 %0, %1;" : "=f"(r) : "f"(e + 1.0f));
    return fmaf(-2.0f, r, 1.0f);
}

// 64-thread CTA (2 warps) handles FOUR batch elements (4-way ILP).
// Lane L (0..63):
//   - layer 1: computes h1 unit L for all 4 elements (1 fma + 1 tanh each)
//   - publishes h via SMEM; layer-2 reads are broadcast LDS.128
//   - layer 2: owns column L; W2 column in 32 packed f32x2 regs;
//     32 ffma2 per element in 2 split chains
//   - reduce: f32x2-packed 5-round butterfly per element-pair (2x fewer shfl)
//     + tiny cross-warp SMEM exchange -> identical gamma on all 64 lanes
__global__ void __launch_bounds__(64)
maxwell_ffnn_kernel(const float* __restrict__ x,
                    const float* __restrict__ W1,
                    const float* __restrict__ b1,
                    const float* __restrict__ W2,
                    const float* __restrict__ b2,
                    const float* __restrict__ W3,
                    const float* __restrict__ b3,
                    float* __restrict__ out) {
    __shared__ __align__(16) float hbuf[4][64];                  // [elem][unit]
    __shared__ __align__(16) unsigned long long red[2][2];       // [warp][pair]

    const int L = threadIdx.x;           // 0..63 = owned h1 unit & layer-2 column

    // ---- loop-invariant weights in registers ----
    const float w1a = __ldg(&W1[L]);         // W1[0][L]
    const float w1b = __ldg(&W1[64 + L]);    // W1[1][L]
    const float b1v = __ldg(&b1[L]);

    unsigned long long w2p[32];              // rows (2s,2s+1) of column L, packed
#pragma unroll
    for (int s = 0; s < 32; ++s)
        w2p[s] = pk2(__ldg(&W2[(2 * s) * 64 + L]),
                     __ldg(&W2[(2 * s + 1) * 64 + L]));

    const float b2v = __ldg(&b2[L]);
    const float w3v = __ldg(&W3[L]);
    const float b3v = __ldg(&b3[0]);

    const float2* xp[4];
    float*        op[4];
#pragma unroll
    for (int e = 0; e < 4; ++e) {
        const int elem = blockIdx.x * 4 + e;
        xp[e] = (const float2*)(x + (size_t)elem * 2048);
        op[e] = out + (size_t)elem * 1024;
    }

    float  gamma[4] = {0.0f, 0.0f, 0.0f, 0.0f};
    float2 xv[4] = {__ldg(&xp[0][0]), __ldg(&xp[1][0]),
                    __ldg(&xp[2][0]), __ldg(&xp[3][0])};
    const unsigned long long zero2 = pk2(0.0f, 0.0f);

#pragma unroll 1
    for (int t = 0; t < 1024; ++t) {
        float eps[4], dtn[4];
#pragma unroll
        for (int e = 0; e < 4; ++e) {
            eps[e] = xv[e].x;
            dtn[e] = xv[e].y;
            if (t < 1023) xv[e] = __ldg(&xp[e][t + 1]);   // prefetch next step
        }

        // ---- layer 1: unit L for all 4 elements ----
#pragma unroll
        for (int e = 0; e < 4; ++e) {
            const float pre = fmaf(gamma[e], w1b, fmaf(eps[e], w1a, b1v));
            hbuf[e][L] = tanh_fast(pre);
        }
        __syncthreads();

        // ---- layer 2 + 3 partial (4 elements, interleaved by compiler) ----
        float gp[4];
#pragma unroll
        for (int e = 0; e < 4; ++e) {
            const ulonglong2* hp = (const ulonglong2*)&hbuf[e][0];
            unsigned long long A0 = pk2(b2v, 0.0f);
            unsigned long long A1 = zero2;
#pragma unroll
            for (int k = 0; k < 16; ++k) {
                const ulonglong2 hh = hp[k];      // h[4k..4k+1] | h[4k+2..4k+3]
                A0 = ffma2(hh.x, w2p[2 * k],     A0);
                A1 = ffma2(hh.y, w2p[2 * k + 1], A1);
            }
            const float2 a = upk2(add2(A0, A1));
            gp[e] = tanh_fast(a.x + a.y) * w3v;
        }

        // ---- packed butterflies (elements 01 and 23 share each shfl) ----
        unsigned long long g01 = pk2(gp[0], gp[1]);
        unsigned long long g23 = pk2(gp[2], gp[3]);
#pragma unroll
        for (int d = 1; d < 32; d <<= 1) {
            g01 = add2(g01, __shfl_xor_sync(FULLMASK, g01, d));
            g23 = add2(g23, __shfl_xor_sync(FULLMASK, g23, d));
        }

        // ---- cross-warp combine via SMEM (2 warps) ----
        const int w = L >> 5;
        if ((L & 31) == 0) {
            red[w][0] = g01;
            red[w][1] = g23;
        }
        __syncthreads();
        g01 = add2(g01, red[w ^ 1][0]);
        g23 = add2(g23, red[w ^ 1][1]);

        const float2 s01 = upk2(g01);
        const float2 s23 = upk2(g23);
        const float sum[4] = {s01.x, s01.y, s23.x, s23.y};

        // ---- gamma update + output (identical on all lanes) ----
#pragma unroll
        for (int e = 0; e < 4; ++e) {
            gamma[e] = fmaf(dtn[e], sum[e] + b3v, gamma[e]);
            // sigma = 0.5*eps + 2*(eps - gamma) = 2.5*eps - 2*gamma
            if (L == e) op[e][t] = fmaf(-2.0f, gamma[e], 2.5f * eps[e]);
        }
    }
}

extern "C" void kernel_launch(void* const* d_in, const int* in_sizes, int n_in,
                              void* d_out, int out_size) {
    (void)in_sizes; (void)n_in; (void)out_size;
    const float* x  = (const float*)d_in[0];
    const float* W1 = (const float*)d_in[1];
    const float* b1 = (const float*)d_in[2];
    const float* W2 = (const float*)d_in[3];
    const float* b2 = (const float*)d_in[4];
    const float* W3 = (const float*)d_in[5];
    const float* b3 = (const float*)d_in[6];
    float* out = (float*)d_out;

    // 4 elements per 64-thread CTA: 512 CTAs = 1024 warps (~7/SM, single wave)
    maxwell_ffnn_kernel<<<512, 64>>>(x, W1, b1, W2, b2, W3, b3, out);
}

// round 6
// speedup vs baseline: 1.0451x; 1.0451x over previous
#include <cuda_runtime.h>

#define FULLMASK 0xffffffffu

// ---------- packed f32x2 helpers (Blackwell sm_103a) ----------
__device__ __forceinline__ unsigned long long pk2(float a, float b) {
    unsigned long long r;
    asm("mov.b64 %0, {%1, %2};" : "=l"(r) : "f"(a), "f"(b));
    return r;
}
__device__ __forceinline__ float2 upk2(unsigned long long v) {
    float2 r;
    asm("mov.b64 {%0, %1}, %2;" : "=f"(r.x), "=f"(r.y) : "l"(v));
    return r;
}
__device__ __forceinline__ unsigned long long ffma2(unsigned long long a,
                                                    unsigned long long b,
                                                    unsigned long long c) {
    unsigned long long d;
    asm("fma.rn.f32x2 %0, %1, %2, %3;" : "=l"(d) : "l"(a), "l"(b), "l"(c));
    return d;
}
__device__ __forceinline__ unsigned long long add2(unsigned long long a,
                                                   unsigned long long b) {
    unsigned long long d;
    asm("add.rn.f32x2 %0, %1, %2;" : "=l"(d) : "l"(a), "l"(b));
    return d;
}

// tanh(x) = 1 - 2/(exp(2x)+1) via MUFU.EX2 + MUFU.RCP (abs err ~1e-7)
__device__ __forceinline__ float tanh_fast(float xx) {
    float e;
    asm("ex2.approx.f32 %0, %1;" : "=f"(e) : "f"(xx * 2.8853900817779268f));
    float r;
    asm("rcp.approx.f32 %0, %1;" : "=f"(r) : "f"(e + 1.0f));
    return fmaf(-2.0f, r, 1.0f);
}

// 2048 warps total: 1024 CTAs x 64 threads, 2 elements per CTA (ILP 2 at TLP 3.46/SMSP).
// Thread L (0..63):
//   layer 1: computes h1 unit L for both elements (1 fma + 1 tanh each)
//   layer 2: owns column L; W2 column in 32 row-packed f32x2 regs (64 regs);
//            per element 32 ffma2 in 2 split chains, h via broadcast LDS.128
//   reduce:  f32x2 elem-packed 5-round butterfly (warp-local 32 columns)
//            + one cross-warp SMEM combine -> identical gammas on all 64 lanes
// hbuf and red are double-buffered by step parity -> only 2 barriers/step.
__global__ void __launch_bounds__(64, 7)
maxwell_ffnn_kernel(const float* __restrict__ x,
                    const float* __restrict__ W1,
                    const float* __restrict__ b1,
                    const float* __restrict__ W2,
                    const float* __restrict__ b2,
                    const float* __restrict__ W3,
                    const float* __restrict__ b3,
                    float* __restrict__ out) {
    __shared__ __align__(16) float hbuf[2][2][64];              // [parity][elem][unit]
    __shared__ __align__(16) unsigned long long red[2][2];      // [parity][warp]

    const int L = threadIdx.x;           // 0..63: owned h1 unit & layer-2 column
    const int w = L >> 5;                // warp id within CTA

    // ---- loop-invariant weights in registers ----
    const float w1a = __ldg(&W1[L]);         // W1[0][L]
    const float w1b = __ldg(&W1[64 + L]);    // W1[1][L]
    const float b1v = __ldg(&b1[L]);

    unsigned long long w2p[32];              // rows (2s,2s+1) of column L
#pragma unroll
    for (int s = 0; s < 32; ++s)
        w2p[s] = pk2(__ldg(&W2[(2 * s) * 64 + L]),
                     __ldg(&W2[(2 * s + 1) * 64 + L]));

    const float b2v = __ldg(&b2[L]);
    const float w3v = __ldg(&W3[L]);
    const float b3v = __ldg(&b3[0]);

    const int e0 = blockIdx.x * 2;
    const float2* xp0 = (const float2*)(x + (size_t)e0 * 2048);
    const float2* xp1 = xp0 + 1024;
    float* op0 = out + (size_t)e0 * 1024;
    float* op1 = op0 + 1024;

    float gamma0 = 0.0f, gamma1 = 0.0f;
    float2 xv0 = __ldg(&xp0[0]);
    float2 xv1 = __ldg(&xp1[0]);
    const unsigned long long zero2 = pk2(0.0f, 0.0f);

#pragma unroll 1
    for (int t = 0; t < 1024; ++t) {
        const float eps0 = xv0.x, dtn0 = xv0.y;
        const float eps1 = xv1.x, dtn1 = xv1.y;
        if (t < 1023) { xv0 = __ldg(&xp0[t + 1]); xv1 = __ldg(&xp1[t + 1]); }

        const int par = t & 1;

        // ---- layer 1: unit L for both elements ----
        hbuf[par][0][L] = tanh_fast(fmaf(gamma0, w1b, fmaf(eps0, w1a, b1v)));
        hbuf[par][1][L] = tanh_fast(fmaf(gamma1, w1b, fmaf(eps1, w1a, b1v)));
        __syncthreads();

        // ---- layer 2: column L, both elements (split chains depth 16) ----
        float gp0, gp1;
        {
            const ulonglong2* hp = (const ulonglong2*)&hbuf[par][0][0];
            unsigned long long A0 = pk2(b2v, 0.0f), A1 = zero2;
#pragma unroll
            for (int k = 0; k < 8; ++k) {
                const ulonglong2 ha = hp[2 * k];
                const ulonglong2 hb = hp[2 * k + 1];
                A0 = ffma2(ha.x, w2p[4 * k],     A0);
                A1 = ffma2(ha.y, w2p[4 * k + 1], A1);
                A0 = ffma2(hb.x, w2p[4 * k + 2], A0);
                A1 = ffma2(hb.y, w2p[4 * k + 3], A1);
            }
            const float2 a = upk2(add2(A0, A1));
            gp0 = tanh_fast(a.x + a.y) * w3v;
        }
        {
            const ulonglong2* hp = (const ulonglong2*)&hbuf[par][1][0];
            unsigned long long A0 = pk2(b2v, 0.0f), A1 = zero2;
#pragma unroll
            for (int k = 0; k < 8; ++k) {
                const ulonglong2 ha = hp[2 * k];
                const ulonglong2 hb = hp[2 * k + 1];
                A0 = ffma2(ha.x, w2p[4 * k],     A0);
                A1 = ffma2(ha.y, w2p[4 * k + 1], A1);
                A0 = ffma2(hb.x, w2p[4 * k + 2], A0);
                A1 = ffma2(hb.y, w2p[4 * k + 3], A1);
            }
            const float2 a = upk2(add2(A0, A1));
            gp1 = tanh_fast(a.x + a.y) * w3v;
        }

        // ---- warp-local reduce over this warp's 32 columns (elem-packed) ----
        unsigned long long g = pk2(gp0, gp1);
#pragma unroll
        for (int d = 1; d < 32; d <<= 1)
            g = add2(g, __shfl_xor_sync(FULLMASK, g, d));

        // ---- cross-warp combine (other warp's 32 columns) ----
        if ((L & 31) == 0) red[par][w] = g;
        __syncthreads();
        g = add2(g, red[par][w ^ 1]);

        const float2 s = upk2(g);
        gamma0 = fmaf(dtn0, s.x + b3v, gamma0);
        gamma1 = fmaf(dtn1, s.y + b3v, gamma1);

        // sigma = 0.5*eps + 2*(eps - gamma) = 2.5*eps - 2*gamma
        if (L == 0) op0[t] = fmaf(-2.0f, gamma0, 2.5f * eps0);
        if (L == 1) op1[t] = fmaf(-2.0f, gamma1, 2.5f * eps1);
    }
}

extern "C" void kernel_launch(void* const* d_in, const int* in_sizes, int n_in,
                              void* d_out, int out_size) {
    (void)in_sizes; (void)n_in; (void)out_size;
    const float* x  = (const float*)d_in[0];
    const float* W1 = (const float*)d_in[1];
    const float* b1 = (const float*)d_in[2];
    const float* W2 = (const float*)d_in[3];
    const float* b2 = (const float*)d_in[4];
    const float* W3 = (const float*)d_in[5];
    const float* b3 = (const float*)d_in[6];
    float* out = (float*)d_out;

    // 2 elements per 64-thread CTA: 1024 CTAs = 2048 warps (13.8/SM, one wave)
    maxwell_ffnn_kernel<<<1024, 64>>>(x, W1, b1, W2, b2, W3, b3, out);
}